// round 15
// baseline (speedup 1.0000x reference)
#include <cuda_runtime.h>
#include <cuda_fp16.h>
#include <cstdint>

// ---------------------------------------------------------------------------
// GAT (3 layers, single head) on GB300 — CSR + fp16-gather + HMMA GEMM,
// single-pass softmax-aggregate with register-chunked high-MLP gather.
//  0: x [N, F_IN] f32
//  1: edge_index [2, E] (runtime-detected int32 vs int64)
//  2..5:  W1 [F_IN,64], a_src1[64], a_dst1[64], b1[64]
//  6..9:  W2, as2, ad2, b2     10..13: W3, as3, ad3, b3
// output: [N, 64] f32
// ---------------------------------------------------------------------------

#define HID 64
#define NMAX 131072
#define EMAX 3400000
#define SCAN_B 512

__device__ __align__(16) int      g_csrc[EMAX];     // CSR: src ids grouped by dst
__device__ __align__(16) int      g_cnt[NMAX];      // histogram, then fill cursor
__device__ __align__(16) int      g_off[NMAX + 1];  // CSR row offsets
__device__ __align__(16) int      g_bsum[1024];
__device__ __align__(16) __half   g_Hh[(size_t)NMAX * HID];  // hidden, fp16 (gather)
__device__ __align__(16) float    g_O[(size_t)NMAX * HID];   // aggregated output
__device__ __align__(16) float    g_es[NMAX];
__device__ __align__(16) float    g_ed[NMAX];
__device__ __align__(16) float    g_selfe[NMAX];
__device__ int g_is32;

__device__ __forceinline__ float leaky(float v) { return v > 0.f ? v : 0.2f * v; }

// ---------------------------------------------------------------------------
// dtype detection: int32 buffer read as u64 packs two ids -> values >= 2^32
// ---------------------------------------------------------------------------
__global__ void detect_dtype(const unsigned long long* __restrict__ ei, int nscan) {
    __shared__ int flag;
    if (threadIdx.x == 0) flag = 0;
    __syncthreads();
    for (int j = threadIdx.x; j < nscan; j += blockDim.x)
        if (ei[j] >= 0x100000000ull) flag = 1;
    __syncthreads();
    if (threadIdx.x == 0) g_is32 = flag;
}

__device__ __forceinline__ int load_id(const void* eiv, size_t idx) {
    if (g_is32) return ((const int*)eiv)[idx];
    return (int)((const long long*)eiv)[idx];
}

// ---------------------------------------------------------------------------
// CSR build — 4 edges per thread for atomic MLP
// ---------------------------------------------------------------------------
__global__ void zero_cnt(int N) {
    int i = blockIdx.x * blockDim.x + threadIdx.x;
    if (i < N) g_cnt[i] = 0;
}
__global__ void hist_k(const void* __restrict__ eiv, int E, int N) {
    int i0 = (blockIdx.x * blockDim.x + threadIdx.x) << 2;
#pragma unroll
    for (int p = 0; p < 4; p++) {
        int i = i0 + p;
        if (i < E) {
            int d = load_id(eiv, (size_t)E + i);
            d = min(max(d, 0), N - 1);
            atomicAdd(&g_cnt[d], 1);
        }
    }
}
__global__ void __launch_bounds__(SCAN_B) scan_block(int N) {
    __shared__ int ws[SCAN_B / 32];
    int tid = threadIdx.x;
    int gi = blockIdx.x * SCAN_B + tid;
    int v = (gi < N) ? g_cnt[gi] : 0;
    int lane = tid & 31, wid = tid >> 5;
    int x = v;
#pragma unroll
    for (int o = 1; o < 32; o <<= 1) {
        int y = __shfl_up_sync(0xffffffffu, x, o);
        if (lane >= o) x += y;
    }
    if (lane == 31) ws[wid] = x;
    __syncthreads();
    if (wid == 0) {
        int t = (lane < SCAN_B / 32) ? ws[lane] : 0;
#pragma unroll
        for (int o = 1; o < SCAN_B / 32; o <<= 1) {
            int y = __shfl_up_sync(0xffffffffu, t, o);
            if (lane >= o) t += y;
        }
        if (lane < SCAN_B / 32) ws[lane] = t;
    }
    __syncthreads();
    int incl = x + (wid > 0 ? ws[wid - 1] : 0);
    if (gi < N) g_off[gi + 1] = incl;
    if (tid == SCAN_B - 1) g_bsum[blockIdx.x] = incl;
}
__global__ void __launch_bounds__(SCAN_B) scan_bsums(int nb) {
    __shared__ int ws[SCAN_B / 32];
    int tid = threadIdx.x;
    int v = (tid < nb) ? g_bsum[tid] : 0;
    int lane = tid & 31, wid = tid >> 5;
    int x = v;
#pragma unroll
    for (int o = 1; o < 32; o <<= 1) {
        int y = __shfl_up_sync(0xffffffffu, x, o);
        if (lane >= o) x += y;
    }
    if (lane == 31) ws[wid] = x;
    __syncthreads();
    if (wid == 0) {
        int t = (lane < SCAN_B / 32) ? ws[lane] : 0;
#pragma unroll
        for (int o = 1; o < SCAN_B / 32; o <<= 1) {
            int y = __shfl_up_sync(0xffffffffu, t, o);
            if (lane >= o) t += y;
        }
        if (lane < SCAN_B / 32) ws[lane] = t;
    }
    __syncthreads();
    int incl = x + (wid > 0 ? ws[wid - 1] : 0);
    if (tid < nb) g_bsum[tid] = incl - v;   // exclusive
}
__global__ void add_offsets(int N) {
    int gi = blockIdx.x * blockDim.x + threadIdx.x;
    if (gi == 0) g_off[0] = 0;
    if (gi < N) g_off[gi + 1] += g_bsum[gi / SCAN_B];
}
__global__ void copy_cursor(int N) {
    int i = blockIdx.x * blockDim.x + threadIdx.x;
    if (i < N) g_cnt[i] = g_off[i];
}
__global__ void fill_csr(const void* __restrict__ eiv, int E, int N) {
    int i0 = (blockIdx.x * blockDim.x + threadIdx.x) << 2;
#pragma unroll
    for (int p = 0; p < 4; p++) {
        int i = i0 + p;
        if (i < E) {
            int s = load_id(eiv, i);
            int d = load_id(eiv, (size_t)E + i);
            s = min(max(s, 0), N - 1);
            d = min(max(d, 0), N - 1);
            int pos = atomicAdd(&g_cnt[d], 1);
            g_csrc[pos] = s;
        }
    }
}

// ---------------------------------------------------------------------------
// HMMA GEMM: act(X[M,K]) @ W[K,64] -> g_Hh (fp16) via mma.sync m16n8k16.
// 128x64 block tile, 8 warps; fp32 accumulators; fused es/ed/selfe epilogue.
// ---------------------------------------------------------------------------
#define KC 32
#define XS_STR 40
template<bool RELU, bool FROM_GO>
__global__ void __launch_bounds__(256)
gemm_k(const float* __restrict__ X, const float* __restrict__ W,
       const float* __restrict__ as, const float* __restrict__ ad,
       int M, int K) {
    __shared__ __half Xs[128 * XS_STR];
    __shared__ __half Wt[64 * XS_STR];

    const int tid = threadIdx.x;
    const int lane = tid & 31;
    const int warp = tid >> 5;
    const int g = lane >> 2;
    const int t = lane & 3;
    const int wr0 = warp << 4;
    const int row0 = blockIdx.x << 7;

    const float* __restrict__ Xp = FROM_GO ? g_O : X;

    float acc[8][4];
#pragma unroll
    for (int n = 0; n < 8; n++)
#pragma unroll
        for (int c = 0; c < 4; c++) acc[n][c] = 0.f;

    for (int kk = 0; kk < K; kk += KC) {
        {
            int r = tid >> 1;
            int c0 = (tid & 1) << 4;
            int grow = row0 + r;
            __half2* xs = (__half2*)&Xs[r * XS_STR + c0];
#pragma unroll
            for (int p = 0; p < 4; p++) {
                float4 v = make_float4(0.f, 0.f, 0.f, 0.f);
                if (grow < M)
                    v = *(const float4*)&Xp[(size_t)grow * K + kk + c0 + (p << 2)];
                if (RELU) {
                    v.x = fmaxf(v.x, 0.f); v.y = fmaxf(v.y, 0.f);
                    v.z = fmaxf(v.z, 0.f); v.w = fmaxf(v.w, 0.f);
                }
                xs[p * 2 + 0] = __floats2half2_rn(v.x, v.y);
                xs[p * 2 + 1] = __floats2half2_rn(v.z, v.w);
            }
        }
        {
#pragma unroll
            for (int i = 0; i < 4; i++) {
                int k = warp + (i << 3);
                float w0 = W[(size_t)(kk + k) * HID + lane];
                float w1 = W[(size_t)(kk + k) * HID + lane + 32];
                Wt[lane * XS_STR + k]        = __float2half_rn(w0);
                Wt[(lane + 32) * XS_STR + k] = __float2half_rn(w1);
            }
        }
        __syncthreads();

#pragma unroll
        for (int ks = 0; ks < 2; ks++) {
            int k0 = ks << 4;
            uint32_t a0 = *(uint32_t*)&Xs[(wr0 + g) * XS_STR + k0 + 2 * t];
            uint32_t a1 = *(uint32_t*)&Xs[(wr0 + g + 8) * XS_STR + k0 + 2 * t];
            uint32_t a2 = *(uint32_t*)&Xs[(wr0 + g) * XS_STR + k0 + 2 * t + 8];
            uint32_t a3 = *(uint32_t*)&Xs[(wr0 + g + 8) * XS_STR + k0 + 2 * t + 8];
#pragma unroll
            for (int n = 0; n < 8; n++) {
                uint32_t b0 = *(uint32_t*)&Wt[(n * 8 + g) * XS_STR + k0 + 2 * t];
                uint32_t b1 = *(uint32_t*)&Wt[(n * 8 + g) * XS_STR + k0 + 2 * t + 8];
                asm volatile(
                    "mma.sync.aligned.m16n8k16.row.col.f32.f16.f16.f32 "
                    "{%0,%1,%2,%3}, {%4,%5,%6,%7}, {%8,%9}, {%0,%1,%2,%3};"
                    : "+f"(acc[n][0]), "+f"(acc[n][1]), "+f"(acc[n][2]), "+f"(acc[n][3])
                    : "r"(a0), "r"(a1), "r"(a2), "r"(a3), "r"(b0), "r"(b1));
            }
        }
        __syncthreads();
    }

    int rowA = row0 + wr0 + g;
    int rowB = rowA + 8;
#pragma unroll
    for (int n = 0; n < 8; n++) {
        int col = n * 8 + 2 * t;
        if (rowA < M)
            *(__half2*)&g_Hh[(size_t)rowA * HID + col] = __floats2half2_rn(acc[n][0], acc[n][1]);
        if (rowB < M)
            *(__half2*)&g_Hh[(size_t)rowB * HID + col] = __floats2half2_rn(acc[n][2], acc[n][3]);
    }

    float esA = 0.f, edA = 0.f, esB = 0.f, edB = 0.f;
#pragma unroll
    for (int n = 0; n < 8; n++) {
        int col = n * 8 + 2 * t;
        float s0 = __ldg(&as[col]), s1 = __ldg(&as[col + 1]);
        float d0 = __ldg(&ad[col]), d1 = __ldg(&ad[col + 1]);
        esA += acc[n][0] * s0 + acc[n][1] * s1;
        edA += acc[n][0] * d0 + acc[n][1] * d1;
        esB += acc[n][2] * s0 + acc[n][3] * s1;
        edB += acc[n][2] * d0 + acc[n][3] * d1;
    }
#pragma unroll
    for (int o = 1; o < 4; o <<= 1) {
        esA += __shfl_xor_sync(0xffffffffu, esA, o);
        edA += __shfl_xor_sync(0xffffffffu, edA, o);
        esB += __shfl_xor_sync(0xffffffffu, esB, o);
        edB += __shfl_xor_sync(0xffffffffu, edB, o);
    }
    if (t == 0) {
        if (rowA < M) {
            g_es[rowA] = esA; g_ed[rowA] = edA; g_selfe[rowA] = leaky(esA + edA);
        }
        if (rowB < M) {
            g_es[rowB] = esB; g_ed[rowB] = edB; g_selfe[rowB] = leaky(esB + edB);
        }
    }
}

// ---------------------------------------------------------------------------
// Single-pass softmax + aggregate, register-chunked for MLP.
// Per 32-edge chunk: lane j loads csrc[base+j] (coalesced) and es[idx]
// (32 independent random scalars in flight), computes ex_j. Feature loop
// (unrolled 16x, 2 edges/iter) shuffles idx/ex out of registers -> all
// feature gathers are address-independent -> deep load pipelining.
// Softmax shifted by selfe (shift-invariant; self weight = 1).
// ---------------------------------------------------------------------------
template<bool FINAL>
__global__ void __launch_bounds__(256)
agg_k(const float* __restrict__ b, float* __restrict__ out, int N) {
    int node = (blockIdx.x * 256 + threadIdx.x) >> 5;
    int lane = threadIdx.x & 31;
    if (node >= N) return;

    int beg = g_off[node], end = g_off[node + 1];
    float edn = g_ed[node];
    float selfe = g_selfe[node];

    int half_ = lane >> 4;
    int q = (lane & 15) << 2;

    float ssum = (lane == 0) ? 1.f : 0.f;    // self term exp(0)=1
    float4 acc = make_float4(0.f, 0.f, 0.f, 0.f);
    if (half_ == 0) {                         // self contribution, weight 1
        float2 raw = *(const float2*)&g_Hh[(size_t)node * HID + q];
        __half2 h0 = *(__half2*)&raw.x;
        __half2 h1 = *(__half2*)&raw.y;
        float2 lo = __half22float2(h0), hi = __half22float2(h1);
        acc.x = lo.x; acc.y = lo.y; acc.z = hi.x; acc.w = hi.y;
    }

    for (int base = beg; base < end; base += 32) {
        int cnt = end - base;
        if (cnt > 32) cnt = 32;

        int idx = 0;
        float ex = 0.f;
        if (lane < cnt) {
            idx = g_csrc[base + lane];
            ex = __expf(leaky(g_es[idx] + edn) - selfe);
        }
        ssum += ex;

#pragma unroll
        for (int j = 0; j < 32; j += 2) {
            int j2 = j + half_;
            int s   = __shfl_sync(0xffffffffu, idx, j2);
            float w = __shfl_sync(0xffffffffu, ex, j2);
            if (j2 < cnt) {
                float2 raw = *(const float2*)&g_Hh[(size_t)s * HID + q];
                __half2 h0 = *(__half2*)&raw.x;
                __half2 h1 = *(__half2*)&raw.y;
                float2 lo = __half22float2(h0), hi = __half22float2(h1);
                acc.x += w * lo.x; acc.y += w * lo.y;
                acc.z += w * hi.x; acc.w += w * hi.y;
            }
        }
    }

    // reduce: acc across the two halves, ssum across all lanes
    acc.x += __shfl_xor_sync(0xffffffffu, acc.x, 16);
    acc.y += __shfl_xor_sync(0xffffffffu, acc.y, 16);
    acc.z += __shfl_xor_sync(0xffffffffu, acc.z, 16);
    acc.w += __shfl_xor_sync(0xffffffffu, acc.w, 16);
#pragma unroll
    for (int o = 16; o; o >>= 1) ssum += __shfl_xor_sync(0xffffffffu, ssum, o);

    if (half_ == 0) {
        float inv = 1.f / ssum;
        float4 b4 = *(const float4*)&b[q];
        float* dst = FINAL ? out : g_O;
        *(float4*)&dst[(size_t)node * HID + q] =
            make_float4(acc.x * inv + b4.x, acc.y * inv + b4.y,
                        acc.z * inv + b4.z, acc.w * inv + b4.w);
    }
}

// ---------------------------------------------------------------------------
// host driver
// ---------------------------------------------------------------------------
extern "C" void kernel_launch(void* const* d_in, const int* in_sizes, int n_in,
                              void* d_out, int out_size) {
    const float* x   = (const float*)d_in[0];
    const void*  ei  = d_in[1];
    const float* W1  = (const float*)d_in[2];
    const float* as1 = (const float*)d_in[3];
    const float* ad1 = (const float*)d_in[4];
    const float* b1  = (const float*)d_in[5];
    const float* W2  = (const float*)d_in[6];
    const float* as2 = (const float*)d_in[7];
    const float* ad2 = (const float*)d_in[8];
    const float* b2  = (const float*)d_in[9];
    const float* W3  = (const float*)d_in[10];
    const float* as3 = (const float*)d_in[11];
    const float* ad3 = (const float*)d_in[12];
    const float* b3  = (const float*)d_in[13];

    int hid = in_sizes[3];            // 64
    int fin = in_sizes[2] / hid;      // 128
    int N   = in_sizes[0] / fin;
    int E   = in_sizes[1] / 2;
    float* out = (float*)d_out;

    // edge index dtype detect
    int nscan = 4096;
    if (nscan > E / 2) nscan = E / 2 > 0 ? E / 2 : 1;
    detect_dtype<<<1, 256>>>((const unsigned long long*)ei, nscan);

    // CSR build (once, reused by 3 layers)
    int nb = (N + SCAN_B - 1) / SCAN_B;
    int e4 = (E + 3) / 4;
    zero_cnt<<<(N + 255) / 256, 256>>>(N);
    hist_k<<<(e4 + 255) / 256, 256>>>(ei, E, N);
    scan_block<<<nb, SCAN_B>>>(N);
    scan_bsums<<<1, SCAN_B>>>(nb);
    add_offsets<<<(N + 255) / 256, 256>>>(N);
    copy_cursor<<<(N + 255) / 256, 256>>>(N);
    fill_csr<<<(e4 + 255) / 256, 256>>>(ei, E, N);

    int gblk = (N + 127) / 128;
    int ablk = (N * 32 + 255) / 256;

    // layer 1
    gemm_k<false, false><<<gblk, 256>>>(x, W1, as1, ad1, N, fin);
    agg_k<false><<<ablk, 256>>>(b1, nullptr, N);
    // layer 2
    gemm_k<true, true><<<gblk, 256>>>(nullptr, W2, as2, ad2, N, hid);
    agg_k<false><<<ablk, 256>>>(b2, nullptr, N);
    // layer 3
    gemm_k<true, true><<<gblk, 256>>>(nullptr, W3, as3, ad3, N, hid);
    agg_k<true><<<ablk, 256>>>(b3, out, N);
}

// round 16
// speedup vs baseline: 1.2698x; 1.2698x over previous
#include <cuda_runtime.h>
#include <cuda_fp16.h>
#include <cstdint>

// ---------------------------------------------------------------------------
// GAT (3 layers, single head) on GB300 — CSR + fp16-gather + HMMA GEMM,
// single-pass aggregate with 4-edge-wide independent gathers.
//  0: x [N, F_IN] f32
//  1: edge_index [2, E] (runtime-detected int32 vs int64)
//  2..5:  W1 [F_IN,64], a_src1[64], a_dst1[64], b1[64]
//  6..9:  W2, as2, ad2, b2     10..13: W3, as3, ad3, b3
// output: [N, 64] f32
// ---------------------------------------------------------------------------

#define HID 64
#define NMAX 131072
#define EMAX 3400000
#define SCAN_B 512

__device__ __align__(16) int      g_csrc[EMAX];     // CSR: src ids grouped by dst
__device__ __align__(16) int      g_cnt[NMAX];      // histogram, then fill cursor
__device__ __align__(16) int      g_off[NMAX + 1];  // CSR row offsets
__device__ __align__(16) int      g_bsum[1024];
__device__ __align__(16) __half   g_Hh[(size_t)NMAX * HID];  // hidden, fp16 (gather)
__device__ __align__(16) float    g_O[(size_t)NMAX * HID];   // aggregated output
__device__ __align__(16) float    g_es[NMAX];
__device__ __align__(16) float    g_ed[NMAX];
__device__ __align__(16) float    g_selfe[NMAX];
__device__ int g_is32;

__device__ __forceinline__ float leaky(float v) { return v > 0.f ? v : 0.2f * v; }

// ---------------------------------------------------------------------------
// dtype detection: int32 buffer read as u64 packs two ids -> values >= 2^32
// ---------------------------------------------------------------------------
__global__ void detect_dtype(const unsigned long long* __restrict__ ei, int nscan) {
    __shared__ int flag;
    if (threadIdx.x == 0) flag = 0;
    __syncthreads();
    for (int j = threadIdx.x; j < nscan; j += blockDim.x)
        if (ei[j] >= 0x100000000ull) flag = 1;
    __syncthreads();
    if (threadIdx.x == 0) g_is32 = flag;
}

__device__ __forceinline__ int load_id(const void* eiv, size_t idx) {
    if (g_is32) return ((const int*)eiv)[idx];
    return (int)((const long long*)eiv)[idx];
}

// ---------------------------------------------------------------------------
// CSR build (coalesced 1-edge/thread; edge_index read directly)
// ---------------------------------------------------------------------------
__global__ void zero_cnt(int N) {
    int i = blockIdx.x * blockDim.x + threadIdx.x;
    if (i < N) g_cnt[i] = 0;
}
__global__ void hist_k(const void* __restrict__ eiv, int E, int N) {
    int i = blockIdx.x * blockDim.x + threadIdx.x;
    if (i >= E) return;
    int d = load_id(eiv, (size_t)E + i);
    d = min(max(d, 0), N - 1);
    atomicAdd(&g_cnt[d], 1);
}
__global__ void __launch_bounds__(SCAN_B) scan_block(int N) {
    __shared__ int ws[SCAN_B / 32];
    int tid = threadIdx.x;
    int gi = blockIdx.x * SCAN_B + tid;
    int v = (gi < N) ? g_cnt[gi] : 0;
    int lane = tid & 31, wid = tid >> 5;
    int x = v;
#pragma unroll
    for (int o = 1; o < 32; o <<= 1) {
        int y = __shfl_up_sync(0xffffffffu, x, o);
        if (lane >= o) x += y;
    }
    if (lane == 31) ws[wid] = x;
    __syncthreads();
    if (wid == 0) {
        int t = (lane < SCAN_B / 32) ? ws[lane] : 0;
#pragma unroll
        for (int o = 1; o < SCAN_B / 32; o <<= 1) {
            int y = __shfl_up_sync(0xffffffffu, t, o);
            if (lane >= o) t += y;
        }
        if (lane < SCAN_B / 32) ws[lane] = t;
    }
    __syncthreads();
    int incl = x + (wid > 0 ? ws[wid - 1] : 0);
    if (gi < N) g_off[gi + 1] = incl;
    if (tid == SCAN_B - 1) g_bsum[blockIdx.x] = incl;
}
__global__ void __launch_bounds__(SCAN_B) scan_bsums(int nb) {
    __shared__ int ws[SCAN_B / 32];
    int tid = threadIdx.x;
    int v = (tid < nb) ? g_bsum[tid] : 0;
    int lane = tid & 31, wid = tid >> 5;
    int x = v;
#pragma unroll
    for (int o = 1; o < 32; o <<= 1) {
        int y = __shfl_up_sync(0xffffffffu, x, o);
        if (lane >= o) x += y;
    }
    if (lane == 31) ws[wid] = x;
    __syncthreads();
    if (wid == 0) {
        int t = (lane < SCAN_B / 32) ? ws[lane] : 0;
#pragma unroll
        for (int o = 1; o < SCAN_B / 32; o <<= 1) {
            int y = __shfl_up_sync(0xffffffffu, t, o);
            if (lane >= o) t += y;
        }
        if (lane < SCAN_B / 32) ws[lane] = t;
    }
    __syncthreads();
    int incl = x + (wid > 0 ? ws[wid - 1] : 0);
    if (tid < nb) g_bsum[tid] = incl - v;   // exclusive
}
__global__ void add_offsets(int N) {
    int gi = blockIdx.x * blockDim.x + threadIdx.x;
    if (gi == 0) g_off[0] = 0;
    if (gi < N) g_off[gi + 1] += g_bsum[gi / SCAN_B];
}
__global__ void copy_cursor(int N) {
    int i = blockIdx.x * blockDim.x + threadIdx.x;
    if (i < N) g_cnt[i] = g_off[i];
}
__global__ void fill_csr(const void* __restrict__ eiv, int E, int N) {
    int i = blockIdx.x * blockDim.x + threadIdx.x;
    if (i >= E) return;
    int s = load_id(eiv, i);
    int d = load_id(eiv, (size_t)E + i);
    s = min(max(s, 0), N - 1);
    d = min(max(d, 0), N - 1);
    int pos = atomicAdd(&g_cnt[d], 1);
    g_csrc[pos] = s;
}

// ---------------------------------------------------------------------------
// HMMA GEMM: act(X[M,K]) @ W[K,64] -> g_Hh (fp16) via mma.sync m16n8k16.
// 128x64 block tile, 8 warps; fp32 accumulators; fused es/ed/selfe epilogue.
// ---------------------------------------------------------------------------
#define KC 32
#define XS_STR 40
template<bool RELU, bool FROM_GO>
__global__ void __launch_bounds__(256)
gemm_k(const float* __restrict__ X, const float* __restrict__ W,
       const float* __restrict__ as, const float* __restrict__ ad,
       int M, int K) {
    __shared__ __half Xs[128 * XS_STR];
    __shared__ __half Wt[64 * XS_STR];

    const int tid = threadIdx.x;
    const int lane = tid & 31;
    const int warp = tid >> 5;
    const int g = lane >> 2;
    const int t = lane & 3;
    const int wr0 = warp << 4;
    const int row0 = blockIdx.x << 7;

    const float* __restrict__ Xp = FROM_GO ? g_O : X;

    float acc[8][4];
#pragma unroll
    for (int n = 0; n < 8; n++)
#pragma unroll
        for (int c = 0; c < 4; c++) acc[n][c] = 0.f;

    for (int kk = 0; kk < K; kk += KC) {
        {
            int r = tid >> 1;
            int c0 = (tid & 1) << 4;
            int grow = row0 + r;
            __half2* xs = (__half2*)&Xs[r * XS_STR + c0];
#pragma unroll
            for (int p = 0; p < 4; p++) {
                float4 v = make_float4(0.f, 0.f, 0.f, 0.f);
                if (grow < M)
                    v = *(const float4*)&Xp[(size_t)grow * K + kk + c0 + (p << 2)];
                if (RELU) {
                    v.x = fmaxf(v.x, 0.f); v.y = fmaxf(v.y, 0.f);
                    v.z = fmaxf(v.z, 0.f); v.w = fmaxf(v.w, 0.f);
                }
                xs[p * 2 + 0] = __floats2half2_rn(v.x, v.y);
                xs[p * 2 + 1] = __floats2half2_rn(v.z, v.w);
            }
        }
        {
#pragma unroll
            for (int i = 0; i < 4; i++) {
                int k = warp + (i << 3);
                float w0 = W[(size_t)(kk + k) * HID + lane];
                float w1 = W[(size_t)(kk + k) * HID + lane + 32];
                Wt[lane * XS_STR + k]        = __float2half_rn(w0);
                Wt[(lane + 32) * XS_STR + k] = __float2half_rn(w1);
            }
        }
        __syncthreads();

#pragma unroll
        for (int ks = 0; ks < 2; ks++) {
            int k0 = ks << 4;
            uint32_t a0 = *(uint32_t*)&Xs[(wr0 + g) * XS_STR + k0 + 2 * t];
            uint32_t a1 = *(uint32_t*)&Xs[(wr0 + g + 8) * XS_STR + k0 + 2 * t];
            uint32_t a2 = *(uint32_t*)&Xs[(wr0 + g) * XS_STR + k0 + 2 * t + 8];
            uint32_t a3 = *(uint32_t*)&Xs[(wr0 + g + 8) * XS_STR + k0 + 2 * t + 8];
#pragma unroll
            for (int n = 0; n < 8; n++) {
                uint32_t b0 = *(uint32_t*)&Wt[(n * 8 + g) * XS_STR + k0 + 2 * t];
                uint32_t b1 = *(uint32_t*)&Wt[(n * 8 + g) * XS_STR + k0 + 2 * t + 8];
                asm volatile(
                    "mma.sync.aligned.m16n8k16.row.col.f32.f16.f16.f32 "
                    "{%0,%1,%2,%3}, {%4,%5,%6,%7}, {%8,%9}, {%0,%1,%2,%3};"
                    : "+f"(acc[n][0]), "+f"(acc[n][1]), "+f"(acc[n][2]), "+f"(acc[n][3])
                    : "r"(a0), "r"(a1), "r"(a2), "r"(a3), "r"(b0), "r"(b1));
            }
        }
        __syncthreads();
    }

    int rowA = row0 + wr0 + g;
    int rowB = rowA + 8;
#pragma unroll
    for (int n = 0; n < 8; n++) {
        int col = n * 8 + 2 * t;
        if (rowA < M)
            *(__half2*)&g_Hh[(size_t)rowA * HID + col] = __floats2half2_rn(acc[n][0], acc[n][1]);
        if (rowB < M)
            *(__half2*)&g_Hh[(size_t)rowB * HID + col] = __floats2half2_rn(acc[n][2], acc[n][3]);
    }

    float esA = 0.f, edA = 0.f, esB = 0.f, edB = 0.f;
#pragma unroll
    for (int n = 0; n < 8; n++) {
        int col = n * 8 + 2 * t;
        float s0 = __ldg(&as[col]), s1 = __ldg(&as[col + 1]);
        float d0 = __ldg(&ad[col]), d1 = __ldg(&ad[col + 1]);
        esA += acc[n][0] * s0 + acc[n][1] * s1;
        edA += acc[n][0] * d0 + acc[n][1] * d1;
        esB += acc[n][2] * s0 + acc[n][3] * s1;
        edB += acc[n][2] * d0 + acc[n][3] * d1;
    }
#pragma unroll
    for (int o = 1; o < 4; o <<= 1) {
        esA += __shfl_xor_sync(0xffffffffu, esA, o);
        edA += __shfl_xor_sync(0xffffffffu, edA, o);
        esB += __shfl_xor_sync(0xffffffffu, esB, o);
        edB += __shfl_xor_sync(0xffffffffu, edB, o);
    }
    if (t == 0) {
        if (rowA < M) {
            g_es[rowA] = esA; g_ed[rowA] = edA; g_selfe[rowA] = leaky(esA + edA);
        }
        if (rowB < M) {
            g_es[rowB] = esB; g_ed[rowB] = edB; g_selfe[rowB] = leaky(esB + edB);
        }
    }
}

// ---------------------------------------------------------------------------
// Single-pass softmax + aggregate: one warp per dst node, zero atomics.
// 8 lanes per edge (float4 of 8 halves each), 4 edges in flight per iter:
// 4 address-independent 128B gathers per loop step. Softmax shifted by
// selfe (shift-invariant, self weight = 1). Group-redundant csrc/es loads
// are LSU broadcasts; redundant exp proven free (R13==R14).
// ---------------------------------------------------------------------------
template<bool FINAL>
__global__ void __launch_bounds__(256)
agg_k(const float* __restrict__ b, float* __restrict__ out, int N) {
    int node = (blockIdx.x * 256 + threadIdx.x) >> 5;
    int lane = threadIdx.x & 31;
    if (node >= N) return;

    int beg = g_off[node], end = g_off[node + 1];
    float edn = g_ed[node];
    float selfe = g_selfe[node];

    int sub = lane >> 3;          // edge slot 0..3
    int sl  = lane & 7;           // lane within 8-group
    int q   = sl << 3;            // 8 halves per lane

    float a0 = 0.f, a1 = 0.f, a2 = 0.f, a3 = 0.f;
    float a4 = 0.f, a5 = 0.f, a6 = 0.f, a7 = 0.f;
    float ssum = (lane == 0) ? 1.f : 0.f;      // self: exp(0)=1

    if (sub == 0) {                             // self contribution, weight 1
        float4 raw = *(const float4*)&g_Hh[(size_t)node * HID + q];
        __half2* hp = (__half2*)&raw;
        float2 f0 = __half22float2(hp[0]), f1 = __half22float2(hp[1]);
        float2 f2 = __half22float2(hp[2]), f3 = __half22float2(hp[3]);
        a0 = f0.x; a1 = f0.y; a2 = f1.x; a3 = f1.y;
        a4 = f2.x; a5 = f2.y; a6 = f3.x; a7 = f3.y;
    }

#pragma unroll 2
    for (int i = beg + sub; i < end; i += 4) {
        int s = g_csrc[i];                      // 8-lane broadcast
        float ex = __expf(leaky(g_es[s] + edn) - selfe);
        if (sl == 0) ssum += ex;
        float4 raw = *(const float4*)&g_Hh[(size_t)s * HID + q];
        __half2* hp = (__half2*)&raw;
        float2 f0 = __half22float2(hp[0]), f1 = __half22float2(hp[1]);
        float2 f2 = __half22float2(hp[2]), f3 = __half22float2(hp[3]);
        a0 += ex * f0.x; a1 += ex * f0.y; a2 += ex * f1.x; a3 += ex * f1.y;
        a4 += ex * f2.x; a5 += ex * f2.y; a6 += ex * f3.x; a7 += ex * f3.y;
    }

    // reduce features across the 4 edge-groups (offsets 8, 16)
#pragma unroll
    for (int o = 8; o <= 16; o <<= 1) {
        a0 += __shfl_xor_sync(0xffffffffu, a0, o);
        a1 += __shfl_xor_sync(0xffffffffu, a1, o);
        a2 += __shfl_xor_sync(0xffffffffu, a2, o);
        a3 += __shfl_xor_sync(0xffffffffu, a3, o);
        a4 += __shfl_xor_sync(0xffffffffu, a4, o);
        a5 += __shfl_xor_sync(0xffffffffu, a5, o);
        a6 += __shfl_xor_sync(0xffffffffu, a6, o);
        a7 += __shfl_xor_sync(0xffffffffu, a7, o);
    }
    // reduce ssum across all lanes
#pragma unroll
    for (int o = 16; o; o >>= 1) ssum += __shfl_xor_sync(0xffffffffu, ssum, o);

    if (sub == 0) {
        float inv = 1.f / ssum;
        float4 b4a = *(const float4*)&b[q];
        float4 b4b = *(const float4*)&b[q + 4];
        float* dst = FINAL ? out : g_O;
        *(float4*)&dst[(size_t)node * HID + q] =
            make_float4(a0 * inv + b4a.x, a1 * inv + b4a.y,
                        a2 * inv + b4a.z, a3 * inv + b4a.w);
        *(float4*)&dst[(size_t)node * HID + q + 4] =
            make_float4(a4 * inv + b4b.x, a5 * inv + b4b.y,
                        a6 * inv + b4b.z, a7 * inv + b4b.w);
    }
}

// ---------------------------------------------------------------------------
// host driver
// ---------------------------------------------------------------------------
extern "C" void kernel_launch(void* const* d_in, const int* in_sizes, int n_in,
                              void* d_out, int out_size) {
    const float* x   = (const float*)d_in[0];
    const void*  ei  = d_in[1];
    const float* W1  = (const float*)d_in[2];
    const float* as1 = (const float*)d_in[3];
    const float* ad1 = (const float*)d_in[4];
    const float* b1  = (const float*)d_in[5];
    const float* W2  = (const float*)d_in[6];
    const float* as2 = (const float*)d_in[7];
    const float* ad2 = (const float*)d_in[8];
    const float* b2  = (const float*)d_in[9];
    const float* W3  = (const float*)d_in[10];
    const float* as3 = (const float*)d_in[11];
    const float* ad3 = (const float*)d_in[12];
    const float* b3  = (const float*)d_in[13];

    int hid = in_sizes[3];            // 64
    int fin = in_sizes[2] / hid;      // 128
    int N   = in_sizes[0] / fin;
    int E   = in_sizes[1] / 2;
    float* out = (float*)d_out;

    // edge index dtype detect
    int nscan = 4096;
    if (nscan > E / 2) nscan = E / 2 > 0 ? E / 2 : 1;
    detect_dtype<<<1, 256>>>((const unsigned long long*)ei, nscan);

    // CSR build (once, reused by 3 layers)
    int nb = (N + SCAN_B - 1) / SCAN_B;
    zero_cnt<<<(N + 255) / 256, 256>>>(N);
    hist_k<<<(E + 255) / 256, 256>>>(ei, E, N);
    scan_block<<<nb, SCAN_B>>>(N);
    scan_bsums<<<1, SCAN_B>>>(nb);
    add_offsets<<<(N + 255) / 256, 256>>>(N);
    copy_cursor<<<(N + 255) / 256, 256>>>(N);
    fill_csr<<<(E + 255) / 256, 256>>>(ei, E, N);

    int gblk = (N + 127) / 128;
    int ablk = (N * 32 + 255) / 256;

    // layer 1
    gemm_k<false, false><<<gblk, 256>>>(x, W1, as1, ad1, N, fin);
    agg_k<false><<<ablk, 256>>>(b1, nullptr, N);
    // layer 2
    gemm_k<true, true><<<gblk, 256>>>(nullptr, W2, as2, ad2, N, hid);
    agg_k<false><<<ablk, 256>>>(b2, nullptr, N);
    // layer 3
    gemm_k<true, true><<<gblk, 256>>>(nullptr, W3, as3, ad3, N, hid);
    agg_k<true><<<ablk, 256>>>(b3, out, N);
}